// round 5
// baseline (speedup 1.0000x reference)
#include <cuda_runtime.h>

#define BATCH 16384
#define CH    30
#define GG    49             // 7*7 cells per image
#define CELLS (BATCH * GG)   // 802816
#define TPB   256
#define NBLK  ((CELLS + TPB - 1) / TPB)  // 3136, exact

__device__ double g_partials[NBLK];
__device__ unsigned int g_count = 0;  // atom.inc wraps to 0 each run -> graph-replay safe

__global__ void __launch_bounds__(TPB)
yolo_fused_kernel(const float* __restrict__ pred, const float* __restrict__ labels,
                  float* __restrict__ out) {
    __shared__ double sdata[TPB / 32];
    __shared__ bool is_last;

    const int t   = threadIdx.x;
    const int tid = blockIdx.x * TPB + t;

    // ---- per-cell loss (1 cell per thread, same as R1's 6.0 TB/s loop) ----
    int b    = tid / GG;
    int cell = tid - b * GG;
    int m    = cell / 7;      // dim -2 index -> gx
    int n    = cell - m * 7;  // dim -1 index -> gy

    const float* pb = pred   + (size_t)b * (CH * GG) + cell;
    const float* lb = labels + (size_t)b * (CH * GG) + cell;

    float p0 = pb[0*GG], p1 = pb[1*GG], p2 = pb[2*GG], p3 = pb[3*GG], p4 = pb[4*GG];
    float p5 = pb[5*GG], p6 = pb[6*GG], p7 = pb[7*GG], p8 = pb[8*GG], p9 = pb[9*GG];
    float l0 = lb[0*GG], l1 = lb[1*GG], l2 = lb[2*GG], l3 = lb[3*GG], l4 = lb[4*GG];
    float l5 = lb[5*GG], l6 = lb[6*GG], l7 = lb[7*GG], l8 = lb[8*GG];

    float gx = (float)m, gy = (float)n;
    const float inv = 1.0f / 7.0f;

    // box 1 (pred ch 0..3)
    float cx1 = (p0 + gx) * inv, cy1 = (p1 + gy) * inv;
    float a1x1 = cx1 - p2 * 0.5f, a1y1 = cy1 - p3 * 0.5f;
    float a1x2 = cx1 + p2 * 0.5f, a1y2 = cy1 + p3 * 0.5f;
    // box 2 (pred ch 5..8)
    float cx2 = (p5 + gx) * inv, cy2 = (p6 + gy) * inv;
    float a2x1 = cx2 - p7 * 0.5f, a2y1 = cy2 - p8 * 0.5f;
    float a2x2 = cx2 + p7 * 0.5f, a2y2 = cy2 + p8 * 0.5f;
    // gt box (labels ch 0..3)
    float cxg = (l0 + gx) * inv, cyg = (l1 + gy) * inv;
    float bx1 = cxg - l2 * 0.5f, by1 = cyg - l3 * 0.5f;
    float bx2 = cxg + l2 * 0.5f, by2 = cyg + l3 * 0.5f;

    float areaB = (bx2 - bx1) * (by2 - by1);

    // iou1
    float ix1 = fmaxf(a1x1, bx1), iy1 = fmaxf(a1y1, by1);
    float ix2 = fminf(a1x2, bx2), iy2 = fminf(a1y2, by2);
    float inter1 = fmaxf(ix2 - ix1, 0.0f) * fmaxf(iy2 - iy1, 0.0f);
    float areaA1 = (a1x2 - a1x1) * (a1y2 - a1y1);
    float iou1 = (inter1 > 0.0f) ? inter1 / (areaA1 + areaB - inter1) : 0.0f;

    // iou2
    float jx1 = fmaxf(a2x1, bx1), jy1 = fmaxf(a2y1, by1);
    float jx2 = fminf(a2x2, bx2), jy2 = fminf(a2y2, by2);
    float inter2 = fmaxf(jx2 - jx1, 0.0f) * fmaxf(jy2 - jy1, 0.0f);
    float areaA2 = (a2x2 - a2x1) * (a2y2 - a2y1);
    float iou2 = (inter2 > 0.0f) ? inter2 / (areaA2 + areaB - inter2) : 0.0f;

    bool resp1 = iou1 > iou2;
    float obj = (l4 == 1.0f) ? 1.0f : 0.0f;

    float d0 = p0 - l0, d1 = p1 - l1;
    float s2 = sqrtf(p2) - sqrtf(l2), s3 = sqrtf(p3) - sqrtf(l3);
    float coor1 = d0*d0 + d1*d1 + s2*s2 + s3*s3;
    float e0 = p5 - l5, e1 = p6 - l6;
    float t2 = sqrtf(p7) - sqrtf(l7), t3 = sqrtf(p8) - sqrtf(l8);
    float coor2 = e0*e0 + e1*e1 + t2*t2 + t3*t3;
    float coor = resp1 ? coor1 : coor2;

    float d4 = p4 - iou1, d9 = p9 - iou2;
    float q4 = d4 * d4, q9 = d9 * d9;
    float obj_conf   = resp1 ? q4 : q9;
    float noobj_resp = resp1 ? q9 : q4;

    // class loss: ch 10..29
    float cls = 0.0f;
    #pragma unroll
    for (int c = 10; c < 30; c++) {
        float dc = pb[c * GG] - lb[c * GG];
        cls += dc * dc;
    }

    float contrib = obj * (5.0f * coor + obj_conf + 0.5f * noobj_resp + cls)
                  + (1.0f - obj) * 0.5f * (p4 * p4 + p9 * p9);
    double val = (double)contrib;

    // ---- deterministic block reduction (double) ----
    #pragma unroll
    for (int o = 16; o > 0; o >>= 1)
        val += __shfl_down_sync(0xffffffffu, val, o);

    int lane = t & 31;
    int wid  = t >> 5;
    if (lane == 0) sdata[wid] = val;
    __syncthreads();
    if (wid == 0) {
        val = (lane < TPB / 32) ? sdata[lane] : 0.0;
        #pragma unroll
        for (int o = 4; o > 0; o >>= 1)
            val += __shfl_down_sync(0xffffffffu, val, o);
        if (lane == 0) {
            g_partials[blockIdx.x] = val;          // plain store; ordered by release below
            unsigned prev;
            // release at gpu scope: orders the partial store before the counter bump
            // WITHOUT __threadfence()'s CCTL.IVALL L1 flush. Wraps NBLK-1 -> 0.
            asm volatile("atom.release.gpu.global.inc.u32 %0, [%1], %2;"
                         : "=r"(prev)
                         : "l"(&g_count), "r"((unsigned)(NBLK - 1))
                         : "memory");
            is_last = (prev == NBLK - 1);
        }
    }
    __syncthreads();

    if (is_last) {
        // last-arriving block: deterministic final reduction.
        // acquire loads hit L2 (never stale L1) and pair with producers' releases.
        double acc = 0.0;
        #pragma unroll
        for (int k = 0; k < NBLK / TPB; k++) {   // 3136/256 = 12.25 -> 12 full + tail
            double v;
            const double* p = &g_partials[t + k * TPB];
            asm volatile("ld.global.acquire.gpu.f64 %0, [%1];" : "=d"(v) : "l"(p) : "memory");
            acc += v;
        }
        {
            int i = t + (NBLK / TPB) * TPB;
            if (i < NBLK) {
                double v;
                const double* p = &g_partials[i];
                asm volatile("ld.global.acquire.gpu.f64 %0, [%1];" : "=d"(v) : "l"(p) : "memory");
                acc += v;
            }
        }
        #pragma unroll
        for (int o = 16; o > 0; o >>= 1)
            acc += __shfl_down_sync(0xffffffffu, acc, o);
        if (lane == 0) sdata[wid] = acc;
        __syncthreads();
        if (wid == 0) {
            acc = (lane < TPB / 32) ? sdata[lane] : 0.0;
            #pragma unroll
            for (int o = 4; o > 0; o >>= 1)
                acc += __shfl_down_sync(0xffffffffu, acc, o);
            if (lane == 0) out[0] = (float)(acc / 6.0);
        }
    }
}

extern "C" void kernel_launch(void* const* d_in, const int* in_sizes, int n_in,
                              void* d_out, int out_size) {
    const float* pred   = (const float*)d_in[0];
    const float* labels = (const float*)d_in[1];
    float* out = (float*)d_out;

    yolo_fused_kernel<<<NBLK, TPB>>>(pred, labels, out);
}

// round 6
// speedup vs baseline: 1.0161x; 1.0161x over previous
#include <cuda_runtime.h>

#define BATCH 16384
#define CH    30
#define GG    49          // 7*7 cells per image
#define CELLS (BATCH * GG) // 802816
#define TPB   256
#define NBLK  ((CELLS + TPB - 1) / TPB)  // 3136

__device__ double g_partials[NBLK];

__global__ void __launch_bounds__(TPB, 6)
yolo_cell_kernel(const float* __restrict__ pred, const float* __restrict__ labels) {
    int tid = blockIdx.x * TPB + threadIdx.x;
    double val = 0.0;
    {
        int b    = tid / GG;
        int cell = tid - b * GG;
        int m    = cell / 7;      // dim -2 index -> gx
        int n    = cell - m * 7;  // dim -1 index -> gy

        const float* pb = pred   + (size_t)b * (CH * GG) + cell;
        const float* lb = labels + (size_t)b * (CH * GG) + cell;

        float p0 = pb[0*GG], p1 = pb[1*GG], p2 = pb[2*GG], p3 = pb[3*GG], p4 = pb[4*GG];
        float p5 = pb[5*GG], p6 = pb[6*GG], p7 = pb[7*GG], p8 = pb[8*GG], p9 = pb[9*GG];
        float l0 = lb[0*GG], l1 = lb[1*GG], l2 = lb[2*GG], l3 = lb[3*GG], l4 = lb[4*GG];
        float l5 = lb[5*GG], l6 = lb[6*GG], l7 = lb[7*GG], l8 = lb[8*GG];

        float gx = (float)m, gy = (float)n;
        const float inv = 1.0f / 7.0f;

        // box 1 (pred ch 0..3)
        float cx1 = (p0 + gx) * inv, cy1 = (p1 + gy) * inv;
        float a1x1 = cx1 - p2 * 0.5f, a1y1 = cy1 - p3 * 0.5f;
        float a1x2 = cx1 + p2 * 0.5f, a1y2 = cy1 + p3 * 0.5f;
        // box 2 (pred ch 5..8)
        float cx2 = (p5 + gx) * inv, cy2 = (p6 + gy) * inv;
        float a2x1 = cx2 - p7 * 0.5f, a2y1 = cy2 - p8 * 0.5f;
        float a2x2 = cx2 + p7 * 0.5f, a2y2 = cy2 + p8 * 0.5f;
        // gt box (labels ch 0..3)
        float cxg = (l0 + gx) * inv, cyg = (l1 + gy) * inv;
        float bx1 = cxg - l2 * 0.5f, by1 = cyg - l3 * 0.5f;
        float bx2 = cxg + l2 * 0.5f, by2 = cyg + l3 * 0.5f;

        float areaB = (bx2 - bx1) * (by2 - by1);

        // iou1
        float ix1 = fmaxf(a1x1, bx1), iy1 = fmaxf(a1y1, by1);
        float ix2 = fminf(a1x2, bx2), iy2 = fminf(a1y2, by2);
        float inter1 = fmaxf(ix2 - ix1, 0.0f) * fmaxf(iy2 - iy1, 0.0f);
        float areaA1 = (a1x2 - a1x1) * (a1y2 - a1y1);
        float iou1 = (inter1 > 0.0f) ? inter1 / (areaA1 + areaB - inter1) : 0.0f;

        // iou2
        float jx1 = fmaxf(a2x1, bx1), jy1 = fmaxf(a2y1, by1);
        float jx2 = fminf(a2x2, bx2), jy2 = fminf(a2y2, by2);
        float inter2 = fmaxf(jx2 - jx1, 0.0f) * fmaxf(jy2 - jy1, 0.0f);
        float areaA2 = (a2x2 - a2x1) * (a2y2 - a2y1);
        float iou2 = (inter2 > 0.0f) ? inter2 / (areaA2 + areaB - inter2) : 0.0f;

        bool resp1 = iou1 > iou2;
        float obj = (l4 == 1.0f) ? 1.0f : 0.0f;

        float d0 = p0 - l0, d1 = p1 - l1;
        float s2 = sqrtf(p2) - sqrtf(l2), s3 = sqrtf(p3) - sqrtf(l3);
        float coor1 = d0*d0 + d1*d1 + s2*s2 + s3*s3;
        float e0 = p5 - l5, e1 = p6 - l6;
        float t2 = sqrtf(p7) - sqrtf(l7), t3 = sqrtf(p8) - sqrtf(l8);
        float coor2 = e0*e0 + e1*e1 + t2*t2 + t3*t3;
        float coor = resp1 ? coor1 : coor2;

        float d4 = p4 - iou1, d9 = p9 - iou2;
        float q4 = d4 * d4, q9 = d9 * d9;
        float obj_conf   = resp1 ? q4 : q9;
        float noobj_resp = resp1 ? q9 : q4;

        // class loss: ch 10..29
        float cls = 0.0f;
        #pragma unroll
        for (int c = 10; c < 30; c++) {
            float dc = pb[c * GG] - lb[c * GG];
            cls += dc * dc;
        }

        float contrib = obj * (5.0f * coor + obj_conf + 0.5f * noobj_resp + cls)
                      + (1.0f - obj) * 0.5f * (p4 * p4 + p9 * p9);
        val = (double)contrib;
    }

    // deterministic block reduction (double)
    #pragma unroll
    for (int o = 16; o > 0; o >>= 1)
        val += __shfl_down_sync(0xffffffffu, val, o);

    __shared__ double sdata[TPB / 32];
    int lane = threadIdx.x & 31;
    int wid  = threadIdx.x >> 5;
    if (lane == 0) sdata[wid] = val;
    __syncthreads();
    if (wid == 0) {
        val = (lane < TPB / 32) ? sdata[lane] : 0.0;
        #pragma unroll
        for (int o = 4; o > 0; o >>= 1)
            val += __shfl_down_sync(0xffffffffu, val, o);
        if (lane == 0) g_partials[blockIdx.x] = val;
    }
}

__global__ void __launch_bounds__(1024)
yolo_final_kernel(float* __restrict__ out) {
    double val = 0.0;
    for (int i = threadIdx.x; i < NBLK; i += 1024)
        val += g_partials[i];

    #pragma unroll
    for (int o = 16; o > 0; o >>= 1)
        val += __shfl_down_sync(0xffffffffu, val, o);

    __shared__ double sdata[32];
    int lane = threadIdx.x & 31;
    int wid  = threadIdx.x >> 5;
    if (lane == 0) sdata[wid] = val;
    __syncthreads();
    if (wid == 0) {
        val = (lane < 32) ? sdata[lane] : 0.0;
        #pragma unroll
        for (int o = 16; o > 0; o >>= 1)
            val += __shfl_down_sync(0xffffffffu, val, o);
        if (lane == 0) out[0] = (float)(val / 6.0);
    }
}

extern "C" void kernel_launch(void* const* d_in, const int* in_sizes, int n_in,
                              void* d_out, int out_size) {
    const float* pred   = (const float*)d_in[0];
    const float* labels = (const float*)d_in[1];
    float* out = (float*)d_out;

    yolo_cell_kernel<<<NBLK, TPB>>>(pred, labels);
    yolo_final_kernel<<<1, 1024>>>(out);
}

// round 7
// speedup vs baseline: 1.0755x; 1.0585x over previous
#include <cuda_runtime.h>

#define BATCH 16384
#define CH    30
#define GG    49          // 7*7 cells per image
#define CELLS (BATCH * GG) // 802816
#define TPB   256
#define NBLK  ((CELLS + TPB - 1) / TPB)  // 3136

__device__ float g_partials[NBLK];

__global__ void __launch_bounds__(TPB, 4)   // allow ~64 regs -> deeper load batching
yolo_cell_kernel(const float* __restrict__ pred, const float* __restrict__ labels) {
    int tid = blockIdx.x * TPB + threadIdx.x;
    float contrib;
    {
        int b    = tid / GG;
        int cell = tid - b * GG;
        int m    = cell / 7;      // dim -2 index -> gx
        int n    = cell - m * 7;  // dim -1 index -> gy

        const float* pb = pred   + (size_t)b * (CH * GG) + cell;
        const float* lb = labels + (size_t)b * (CH * GG) + cell;

        // streaming loads: one-pass data, evict-first so L2 isn't thrashed
        float p0 = __ldcs(pb + 0*GG), p1 = __ldcs(pb + 1*GG), p2 = __ldcs(pb + 2*GG);
        float p3 = __ldcs(pb + 3*GG), p4 = __ldcs(pb + 4*GG), p5 = __ldcs(pb + 5*GG);
        float p6 = __ldcs(pb + 6*GG), p7 = __ldcs(pb + 7*GG), p8 = __ldcs(pb + 8*GG);
        float p9 = __ldcs(pb + 9*GG);
        float l0 = __ldcs(lb + 0*GG), l1 = __ldcs(lb + 1*GG), l2 = __ldcs(lb + 2*GG);
        float l3 = __ldcs(lb + 3*GG), l4 = __ldcs(lb + 4*GG), l5 = __ldcs(lb + 5*GG);
        float l6 = __ldcs(lb + 6*GG), l7 = __ldcs(lb + 7*GG), l8 = __ldcs(lb + 8*GG);

        float gx = (float)m, gy = (float)n;
        const float inv = 1.0f / 7.0f;

        // box 1 (pred ch 0..3)
        float cx1 = (p0 + gx) * inv, cy1 = (p1 + gy) * inv;
        float a1x1 = cx1 - p2 * 0.5f, a1y1 = cy1 - p3 * 0.5f;
        float a1x2 = cx1 + p2 * 0.5f, a1y2 = cy1 + p3 * 0.5f;
        // box 2 (pred ch 5..8)
        float cx2 = (p5 + gx) * inv, cy2 = (p6 + gy) * inv;
        float a2x1 = cx2 - p7 * 0.5f, a2y1 = cy2 - p8 * 0.5f;
        float a2x2 = cx2 + p7 * 0.5f, a2y2 = cy2 + p8 * 0.5f;
        // gt box (labels ch 0..3)
        float cxg = (l0 + gx) * inv, cyg = (l1 + gy) * inv;
        float bx1 = cxg - l2 * 0.5f, by1 = cyg - l3 * 0.5f;
        float bx2 = cxg + l2 * 0.5f, by2 = cyg + l3 * 0.5f;

        float areaB = (bx2 - bx1) * (by2 - by1);

        // iou1
        float ix1 = fmaxf(a1x1, bx1), iy1 = fmaxf(a1y1, by1);
        float ix2 = fminf(a1x2, bx2), iy2 = fminf(a1y2, by2);
        float inter1 = fmaxf(ix2 - ix1, 0.0f) * fmaxf(iy2 - iy1, 0.0f);
        float areaA1 = (a1x2 - a1x1) * (a1y2 - a1y1);
        float iou1 = (inter1 > 0.0f) ? inter1 / (areaA1 + areaB - inter1) : 0.0f;

        // iou2
        float jx1 = fmaxf(a2x1, bx1), jy1 = fmaxf(a2y1, by1);
        float jx2 = fminf(a2x2, bx2), jy2 = fminf(a2y2, by2);
        float inter2 = fmaxf(jx2 - jx1, 0.0f) * fmaxf(jy2 - jy1, 0.0f);
        float areaA2 = (a2x2 - a2x1) * (a2y2 - a2y1);
        float iou2 = (inter2 > 0.0f) ? inter2 / (areaA2 + areaB - inter2) : 0.0f;

        bool resp1 = iou1 > iou2;
        float obj = (l4 == 1.0f) ? 1.0f : 0.0f;

        float d0 = p0 - l0, d1 = p1 - l1;
        float s2 = sqrtf(p2) - sqrtf(l2), s3 = sqrtf(p3) - sqrtf(l3);
        float coor1 = d0*d0 + d1*d1 + s2*s2 + s3*s3;
        float e0 = p5 - l5, e1 = p6 - l6;
        float t2 = sqrtf(p7) - sqrtf(l7), t3 = sqrtf(p8) - sqrtf(l8);
        float coor2 = e0*e0 + e1*e1 + t2*t2 + t3*t3;
        float coor = resp1 ? coor1 : coor2;

        float d4 = p4 - iou1, d9 = p9 - iou2;
        float q4 = d4 * d4, q9 = d9 * d9;
        float obj_conf   = resp1 ? q4 : q9;
        float noobj_resp = resp1 ? q9 : q4;

        // class loss: ch 10..29
        float cls = 0.0f;
        #pragma unroll
        for (int c = 10; c < 30; c++) {
            float dc = __ldcs(pb + c * GG) - __ldcs(lb + c * GG);
            cls += dc * dc;
        }

        contrib = obj * (5.0f * coor + obj_conf + 0.5f * noobj_resp + cls)
                + (1.0f - obj) * 0.5f * (p4 * p4 + p9 * p9);
    }
    double val = (double)contrib;

    // deterministic block reduction (double)
    #pragma unroll
    for (int o = 16; o > 0; o >>= 1)
        val += __shfl_down_sync(0xffffffffu, val, o);

    __shared__ double sdata[TPB / 32];
    int lane = threadIdx.x & 31;
    int wid  = threadIdx.x >> 5;
    if (lane == 0) sdata[wid] = val;
    __syncthreads();
    if (wid == 0) {
        val = (lane < TPB / 32) ? sdata[lane] : 0.0;
        #pragma unroll
        for (int o = 4; o > 0; o >>= 1)
            val += __shfl_down_sync(0xffffffffu, val, o);
        if (lane == 0) g_partials[blockIdx.x] = (float)val;
    }
}

__global__ void __launch_bounds__(256)
yolo_final_kernel(float* __restrict__ out) {
    // 3136 floats = 784 float4; 256 threads x 4 predicated float4 loads
    const float4* p4v = (const float4*)g_partials;
    double val = 0.0;
    #pragma unroll
    for (int k = 0; k < 4; k++) {
        int i = threadIdx.x + k * 256;
        if (i < 784) {
            float4 v = p4v[i];
            val += (double)v.x + (double)v.y + (double)v.z + (double)v.w;
        }
    }

    #pragma unroll
    for (int o = 16; o > 0; o >>= 1)
        val += __shfl_down_sync(0xffffffffu, val, o);

    __shared__ double sdata[8];
    int lane = threadIdx.x & 31;
    int wid  = threadIdx.x >> 5;
    if (lane == 0) sdata[wid] = val;
    __syncthreads();
    if (wid == 0) {
        val = (lane < 8) ? sdata[lane] : 0.0;
        #pragma unroll
        for (int o = 4; o > 0; o >>= 1)
            val += __shfl_down_sync(0xffffffffu, val, o);
        if (lane == 0) out[0] = (float)(val / 6.0);
    }
}

extern "C" void kernel_launch(void* const* d_in, const int* in_sizes, int n_in,
                              void* d_out, int out_size) {
    const float* pred   = (const float*)d_in[0];
    const float* labels = (const float*)d_in[1];
    float* out = (float*)d_out;

    yolo_cell_kernel<<<NBLK, TPB>>>(pred, labels);
    yolo_final_kernel<<<1, 256>>>(out);
}